// round 16
// baseline (speedup 1.0000x reference)
#include <cuda_runtime.h>
#include <cuda_bf16.h>
#include <math.h>

#define BATCH 64
#define SEQ   196
#define DIMC  768
#define HEADS 12
#define HD    64
#define QKV3  2304           // 3*DIMC
#define BN    (BATCH*SEQ)    // 12544
#define SCALE 0.125f         // HD^-0.5
#define NBLK  (BATCH*HEADS*2)  // 1536 (b,h,q-half)

// ---------------- scratch (no allocation allowed; __device__ globals) -------
__device__ float g_qkv[(size_t)BATCH * SEQ * QKV3];          // [BN, 2304]
__device__ float g_ao[(size_t)BATCH * SEQ * DIMC];           // [BN, 768]

// ---------------- helpers -----------------------------------------------------
__device__ __forceinline__ unsigned f2tf32(float x) {
    unsigned u;
    asm volatile("cvt.rna.tf32.f32 %0, %1;" : "=r"(u) : "f"(x));
    return u;
}

__device__ __forceinline__ void mma_tf32(float (&d)[4], const unsigned (&a)[4],
                                         const unsigned (&b)[2]) {
    asm volatile(
        "mma.sync.aligned.m16n8k8.row.col.f32.tf32.tf32.f32 "
        "{%0,%1,%2,%3}, {%4,%5,%6,%7}, {%8,%9}, {%0,%1,%2,%3};\n"
        : "+f"(d[0]), "+f"(d[1]), "+f"(d[2]), "+f"(d[3])
        : "r"(a[0]), "r"(a[1]), "r"(a[2]), "r"(a[3]), "r"(b[0]), "r"(b[1]));
}

__device__ __forceinline__ void mma_bf16(float (&d)[4], const unsigned (&a)[4],
                                         const unsigned (&b)[2]) {
    asm volatile(
        "mma.sync.aligned.m16n8k16.row.col.f32.bf16.bf16.f32 "
        "{%0,%1,%2,%3}, {%4,%5,%6,%7}, {%8,%9}, {%0,%1,%2,%3};\n"
        : "+f"(d[0]), "+f"(d[1]), "+f"(d[2]), "+f"(d[3])
        : "r"(a[0]), "r"(a[1]), "r"(a[2]), "r"(a[3]), "r"(b[0]), "r"(b[1]));
}

// split (a,b) into hi/lo bf16x2 words; a goes to the LOW half (first k elem)
__device__ __forceinline__ unsigned bsplit2(float a, float b, unsigned& lo) {
    __nv_bfloat162 h = __floats2bfloat162_rn(a, b);
    float2 hf = __bfloat1622float2(h);
    __nv_bfloat162 l = __floats2bfloat162_rn(a - hf.x, b - hf.y);
    lo = *(unsigned*)&l;
    return *(unsigned*)&h;
}

// ---------------- split-BF16 GEMM: C[M,N] = A[M,K] @ B[K,N] (+bias) ---------
// 128x128 block tile, BK=32, 256 threads = 8 warps (4M x 2N), warp 32x64.
// hi/lo bf16x2 planes; 3 m16n8k16 mmas per K=16 slice (hh + hl + lh).
#define TBM 128
#define TBN 128
#define TBK 32
#define A2_STRIDE 20    // words; %32==20 -> banks 20r+tq all distinct
#define B2_STRIDE 136   // words; %32==8  -> banks 8tq+r all distinct

__global__ __launch_bounds__(256, 2)
void gemm_bf16s_kernel(const float* __restrict__ A, const float* __restrict__ B,
                       const float* __restrict__ bias, float* __restrict__ C,
                       int M, int N, int K, int useBias)
{
    __shared__ unsigned Ahi[TBM * A2_STRIDE];   // [m][kp] bf16x2
    __shared__ unsigned Alo[TBM * A2_STRIDE];
    __shared__ unsigned Bhi[16 * B2_STRIDE];    // [kp][n] bf16x2 (kp = k/2)
    __shared__ unsigned Blo[16 * B2_STRIDE];

    const int tid  = threadIdx.x;
    const int lane = tid & 31;
    const int warp = tid >> 5;
    const int r    = lane >> 2;
    const int tq   = lane & 3;
    const int warpM = (warp & 3) * 32;     // 4 warps in M
    const int warpN = (warp >> 2) * 64;    // 2 warps in N

    const int n0 = blockIdx.x * TBN;
    const int m0 = blockIdx.y * TBM;

    float acc[2][8][4];
#pragma unroll
    for (int i = 0; i < 2; i++)
#pragma unroll
        for (int j = 0; j < 8; j++)
#pragma unroll
            for (int t = 0; t < 4; t++) acc[i][j][t] = 0.f;

    for (int k0 = 0; k0 < K; k0 += TBK) {
        // ---- A tile: 128 rows x 32 k -> hi/lo planes (4 float4 per thread)
#pragma unroll
        for (int i = 0; i < 4; i++) {
            int f   = tid + i * 256;          // 0..1023
            int row = f >> 3;                 // 0..127
            int kq  = f & 7;                  // float4 idx; k = 4kq..4kq+3
            float4 v = *(const float4*)(A + (size_t)(m0 + row) * K + k0 + kq * 4);
            unsigned l0, l1;
            unsigned h0 = bsplit2(v.x, v.y, l0);
            unsigned h1 = bsplit2(v.z, v.w, l1);
            int wi = row * A2_STRIDE + kq * 2;
            *(uint2*)&Ahi[wi] = make_uint2(h0, h1);
            *(uint2*)&Alo[wi] = make_uint2(l0, l1);
        }
        // ---- B tile: 32 k x 128 n -> hi/lo planes, packed along k
        //      (2 float4 per thread pair-load of rows 2kp, 2kp+1)
#pragma unroll
        for (int i = 0; i < 2; i++) {
            int f  = tid + i * 256;           // 0..511
            int kp = f >> 5;                  // 0..15
            int nn = (f & 31) * 4;            // 0..124
            float4 u = *(const float4*)(B + (size_t)(k0 + 2 * kp)     * N + n0 + nn);
            float4 w = *(const float4*)(B + (size_t)(k0 + 2 * kp + 1) * N + n0 + nn);
            unsigned lx, ly, lz, lw;
            unsigned hx = bsplit2(u.x, w.x, lx);
            unsigned hy = bsplit2(u.y, w.y, ly);
            unsigned hz = bsplit2(u.z, w.z, lz);
            unsigned hw = bsplit2(u.w, w.w, lw);
            int wi = kp * B2_STRIDE + nn;
            *(uint4*)&Bhi[wi] = make_uint4(hx, hy, hz, hw);
            *(uint4*)&Blo[wi] = make_uint4(lx, ly, lz, lw);
        }
        __syncthreads();

        // ---- compute: 2 k-steps of 16 (kp step 8)
#pragma unroll
        for (int ks = 0; ks < 2; ks++) {
            int kpb = ks * 8;
            // pass 1: B-hi cached -> hh + lh terms
            {
                unsigned bh[8][2];
#pragma unroll
                for (int nt = 0; nt < 8; nt++) {
                    int cb = warpN + nt * 8;
                    bh[nt][0] = Bhi[(kpb + tq)     * B2_STRIDE + cb + r];
                    bh[nt][1] = Bhi[(kpb + tq + 4) * B2_STRIDE + cb + r];
                }
#pragma unroll
                for (int mt = 0; mt < 2; mt++) {
                    int rb = warpM + mt * 16;
                    unsigned ah[4], al[4];
                    ah[0] = Ahi[(rb + r)     * A2_STRIDE + kpb + tq];
                    ah[1] = Ahi[(rb + r + 8) * A2_STRIDE + kpb + tq];
                    ah[2] = Ahi[(rb + r)     * A2_STRIDE + kpb + tq + 4];
                    ah[3] = Ahi[(rb + r + 8) * A2_STRIDE + kpb + tq + 4];
                    al[0] = Alo[(rb + r)     * A2_STRIDE + kpb + tq];
                    al[1] = Alo[(rb + r + 8) * A2_STRIDE + kpb + tq];
                    al[2] = Alo[(rb + r)     * A2_STRIDE + kpb + tq + 4];
                    al[3] = Alo[(rb + r + 8) * A2_STRIDE + kpb + tq + 4];
#pragma unroll
                    for (int nt = 0; nt < 8; nt++) {
                        mma_bf16(acc[mt][nt], ah, bh[nt]);
                        mma_bf16(acc[mt][nt], al, bh[nt]);
                    }
                }
            }
            // pass 2: B-lo cached -> hl term
            {
                unsigned bl[8][2];
#pragma unroll
                for (int nt = 0; nt < 8; nt++) {
                    int cb = warpN + nt * 8;
                    bl[nt][0] = Blo[(kpb + tq)     * B2_STRIDE + cb + r];
                    bl[nt][1] = Blo[(kpb + tq + 4) * B2_STRIDE + cb + r];
                }
#pragma unroll
                for (int mt = 0; mt < 2; mt++) {
                    int rb = warpM + mt * 16;
                    unsigned ah[4];
                    ah[0] = Ahi[(rb + r)     * A2_STRIDE + kpb + tq];
                    ah[1] = Ahi[(rb + r + 8) * A2_STRIDE + kpb + tq];
                    ah[2] = Ahi[(rb + r)     * A2_STRIDE + kpb + tq + 4];
                    ah[3] = Ahi[(rb + r + 8) * A2_STRIDE + kpb + tq + 4];
#pragma unroll
                    for (int nt = 0; nt < 8; nt++)
                        mma_bf16(acc[mt][nt], ah, bl[nt]);
                }
            }
        }
        __syncthreads();
    }

    // ---- epilogue: c0/c1 at (r, 2tq), c2/c3 at (r+8, 2tq)
#pragma unroll
    for (int mt = 0; mt < 2; mt++) {
#pragma unroll
        for (int nt = 0; nt < 8; nt++) {
            int row = m0 + warpM + mt * 16 + r;
            int col = n0 + warpN + nt * 8 + 2 * tq;
            float2 lo = make_float2(acc[mt][nt][0], acc[mt][nt][1]);
            float2 hi = make_float2(acc[mt][nt][2], acc[mt][nt][3]);
            if (useBias) {
                float2 bv = *(const float2*)(bias + col);
                lo.x += bv.x; lo.y += bv.y;
                hi.x += bv.x; hi.y += bv.y;
            }
            *(float2*)(C + (size_t)row * N + col)       = lo;
            *(float2*)(C + (size_t)(row + 8) * N + col) = hi;
        }
    }
}

// ---------------- fused attention: scores + reg softmax + bias + AV ---------
// (R14 kernel, unchanged)
#define FA_KV_OFF 7616                            // words (112*68)
#define FA_SMEM_WORDS (FA_KV_OFF + 208 * 72)      // 22592
#define FA_SMEM_BYTES (FA_SMEM_WORDS * 4)         // 90368

__global__ __launch_bounds__(224, 2)
void attn_fused_kernel(const float* __restrict__ qkv,
                       const float* __restrict__ sa,
                       float* __restrict__ ao)
{
    extern __shared__ unsigned smu[];
    unsigned* Qs = smu;                 // [112][68], SCALE pre-folded
    unsigned* Ks = smu + FA_KV_OFF;     // [208][68] (scores phase)
    unsigned* Vs = smu + FA_KV_OFF;     // [208][72] tf32 (AV phase)

    const int bid = blockIdx.x;
    const int bh = bid >> 1, qb = bid & 1;
    const int b = bh / HEADS, h = bh % HEADS;
    const int q0 = qb * 98;

    const float* Qg = qkv + (size_t)b * SEQ * QKV3 + h * HD;
    const float* Kg = Qg + DIMC;
    const float* Vg = Qg + 2 * DIMC;

    const int tid  = threadIdx.x;
    const int lane = tid & 31;
    const int warp = tid >> 5;
    const int r    = lane >> 2;
    const int tq   = lane & 3;

    for (int i = tid; i < 112 * 16; i += 224) {
        int row = i >> 4, c4 = (i & 15) * 4;
        float4 v = make_float4(0.f, 0.f, 0.f, 0.f);
        if (row < 98) v = *(const float4*)(Qg + (size_t)(q0 + row) * QKV3 + c4);
        uint4 o;
        o.x = f2tf32(v.x * SCALE); o.y = f2tf32(v.y * SCALE);
        o.z = f2tf32(v.z * SCALE); o.w = f2tf32(v.w * SCALE);
        *(uint4*)&Qs[row * 68 + c4] = o;
    }
    for (int i = tid; i < 208 * 16; i += 224) {
        int row = i >> 4, c4 = (i & 15) * 4;
        float4 v = make_float4(0.f, 0.f, 0.f, 0.f);
        if (row < SEQ) v = *(const float4*)(Kg + (size_t)row * QKV3 + c4);
        uint4 o;
        o.x = f2tf32(v.x); o.y = f2tf32(v.y);
        o.z = f2tf32(v.z); o.w = f2tf32(v.w);
        *(uint4*)&Ks[row * 68 + c4] = o;
    }
    __syncthreads();

    float acc[13][2][4];
#pragma unroll
    for (int mg = 0; mg < 13; mg++)
#pragma unroll
        for (int mt = 0; mt < 2; mt++)
#pragma unroll
            for (int t = 0; t < 4; t++) acc[mg][mt][t] = 0.f;

    const int rb = warp * 16;
#pragma unroll
    for (int ks = 0; ks < 8; ks++) {
        int kb = ks * 8;
        unsigned af[4];
        af[0] = Qs[(rb + r)     * 68 + kb + tq];
        af[1] = Qs[(rb + r + 8) * 68 + kb + tq];
        af[2] = Qs[(rb + r)     * 68 + kb + tq + 4];
        af[3] = Qs[(rb + r + 8) * 68 + kb + tq + 4];
#pragma unroll
        for (int mg = 0; mg < 13; mg++)
#pragma unroll
            for (int mt = 0; mt < 2; mt++) {
                int cb = mg * 16 + mt * 8;
                unsigned bf[2];
                bf[0] = Ks[(cb + r) * 68 + kb + tq];
                bf[1] = Ks[(cb + r) * 68 + kb + tq + 4];
                mma_tf32(acc[mg][mt], af, bf);
            }
    }

    float mx0 = -INFINITY, mx1 = -INFINITY;
#pragma unroll
    for (int mg = 0; mg < 13; mg++)
#pragma unroll
        for (int mt = 0; mt < 2; mt++)
#pragma unroll
            for (int j = 0; j < 2; j++) {
                bool valid = (mg < 12) || (mt == 0 && (2 * tq + j) < 4);
                if (valid) {
                    mx0 = fmaxf(mx0, acc[mg][mt][j]);
                    mx1 = fmaxf(mx1, acc[mg][mt][2 + j]);
                }
            }
    mx0 = fmaxf(mx0, __shfl_xor_sync(0xffffffffu, mx0, 1));
    mx0 = fmaxf(mx0, __shfl_xor_sync(0xffffffffu, mx0, 2));
    mx1 = fmaxf(mx1, __shfl_xor_sync(0xffffffffu, mx1, 1));
    mx1 = fmaxf(mx1, __shfl_xor_sync(0xffffffffu, mx1, 2));

    float sum0 = 0.f, sum1 = 0.f;
#pragma unroll
    for (int mg = 0; mg < 13; mg++)
#pragma unroll
        for (int mt = 0; mt < 2; mt++)
#pragma unroll
            for (int j = 0; j < 2; j++) {
                bool valid = (mg < 12) || (mt == 0 && (2 * tq + j) < 4);
                float e0 = valid ? __expf(acc[mg][mt][j]     - mx0) : 0.f;
                float e1 = valid ? __expf(acc[mg][mt][2 + j] - mx1) : 0.f;
                acc[mg][mt][j]     = e0;
                acc[mg][mt][2 + j] = e1;
                sum0 += e0;
                sum1 += e1;
            }
    sum0 += __shfl_xor_sync(0xffffffffu, sum0, 1);
    sum0 += __shfl_xor_sync(0xffffffffu, sum0, 2);
    sum1 += __shfl_xor_sync(0xffffffffu, sum1, 1);
    sum1 += __shfl_xor_sync(0xffffffffu, sum1, 2);
    const float inv0 = 1.f / sum0;
    const float inv1 = 1.f / sum1;

    const int row0 = rb + r, row1 = rb + r + 8;
    const float* ar0 = sa + ((size_t)h * SEQ + q0 + row0) * SEQ;
    const float* ar1 = sa + ((size_t)h * SEQ + q0 + row1) * SEQ;
    const bool rOk0 = row0 < 98, rOk1 = row1 < 98;
#pragma unroll
    for (int mg = 0; mg < 13; mg++)
#pragma unroll
        for (int mt = 0; mt < 2; mt++) {
            int c = mg * 16 + mt * 8 + 2 * tq;
#pragma unroll
            for (int j = 0; j < 2; j++) {
                bool valid = (mg < 12) || (mt == 0 && (2 * tq + j) < 4);
                float a0 = (valid && rOk0) ? ar0[c + j] : 0.f;
                float a1 = (valid && rOk1) ? ar1[c + j] : 0.f;
                acc[mg][mt][j]     = valid ? acc[mg][mt][j]     * inv0 + a0 : 0.f;
                acc[mg][mt][2 + j] = valid ? acc[mg][mt][2 + j] * inv1 + a1 : 0.f;
            }
        }

    __syncthreads();   // all warps done reading Ks
    for (int i = tid; i < 208 * 16; i += 224) {
        int row = i >> 4, c4 = (i & 15) * 4;
        float4 v = make_float4(0.f, 0.f, 0.f, 0.f);
        if (row < SEQ) v = *(const float4*)(Vg + (size_t)row * QKV3 + c4);
        uint4 o;
        o.x = f2tf32(v.x); o.y = f2tf32(v.y);
        o.z = f2tf32(v.z); o.w = f2tf32(v.w);
        *(uint4*)&Vs[row * 72 + c4] = o;
    }
    __syncthreads();

    float out[8][4];
#pragma unroll
    for (int nt = 0; nt < 8; nt++)
#pragma unroll
        for (int t = 0; t < 4; t++) out[nt][t] = 0.f;

    const int srcA = (lane & ~3) | (tq >> 1);
    const int srcB = srcA + 2;
    const bool jsel = (tq & 1);

#pragma unroll
    for (int mg = 0; mg < 13; mg++) {
#pragma unroll
        for (int mt = 0; mt < 2; mt++) {
            float p0a = __shfl_sync(0xffffffffu, acc[mg][mt][0], srcA);
            float p1a = __shfl_sync(0xffffffffu, acc[mg][mt][1], srcA);
            float p0b = __shfl_sync(0xffffffffu, acc[mg][mt][0], srcB);
            float p1b = __shfl_sync(0xffffffffu, acc[mg][mt][1], srcB);
            float p2a = __shfl_sync(0xffffffffu, acc[mg][mt][2], srcA);
            float p3a = __shfl_sync(0xffffffffu, acc[mg][mt][3], srcA);
            float p2b = __shfl_sync(0xffffffffu, acc[mg][mt][2], srcB);
            float p3b = __shfl_sync(0xffffffffu, acc[mg][mt][3], srcB);
            unsigned af[4];
            af[0] = f2tf32(jsel ? p1a : p0a);
            af[1] = f2tf32(jsel ? p3a : p2a);
            af[2] = f2tf32(jsel ? p1b : p0b);
            af[3] = f2tf32(jsel ? p3b : p2b);
            const int kb = mg * 16 + mt * 8;
#pragma unroll
            for (int nt = 0; nt < 8; nt++) {
                unsigned bf[2];
                bf[0] = Vs[(kb + tq)     * 72 + nt * 8 + r];
                bf[1] = Vs[(kb + tq + 4) * 72 + nt * 8 + r];
                mma_tf32(out[nt], af, bf);
            }
        }
    }

    float* og = ao + (size_t)b * SEQ * DIMC + h * HD;
#pragma unroll
    for (int nt = 0; nt < 8; nt++) {
        int c = nt * 8 + 2 * tq;
        if (rOk0)
            *(float2*)(og + (size_t)(q0 + row0) * DIMC + c) =
                make_float2(out[nt][0], out[nt][1]);
        if (rOk1)
            *(float2*)(og + (size_t)(q0 + row1) * DIMC + c) =
                make_float2(out[nt][2], out[nt][3]);
    }
}

// ---------------- launch ----------------------------------------------------
extern "C" void kernel_launch(void* const* d_in, const int* in_sizes, int n_in,
                              void* d_out, int out_size)
{
    const float* x     = (const float*)d_in[0];  // [64,196,768]
    const float* Wqkv  = (const float*)d_in[1];  // [768,2304]
    const float* sa    = (const float*)d_in[2];  // [1,12,196,196]
    const float* Wproj = (const float*)d_in[3];  // [768,768]
    const float* bproj = (const float*)d_in[4];  // [768]
    float* out = (float*)d_out;                  // [64,196,768]

    void *p_qkv, *p_ao;
    cudaGetSymbolAddress(&p_qkv, g_qkv);
    cudaGetSymbolAddress(&p_ao, g_ao);
    float* qkv = (float*)p_qkv;
    float* ao  = (float*)p_ao;

    static int smem_set = 0;
    if (!smem_set) {
        cudaFuncSetAttribute(attn_fused_kernel,
                             cudaFuncAttributeMaxDynamicSharedMemorySize,
                             FA_SMEM_BYTES);
        smem_set = 1;
    }

    // 1) QKV GEMM (split-bf16, m16n8k16)
    gemm_bf16s_kernel<<<dim3(QKV3 / TBN, BN / TBM), 256>>>(x, Wqkv, nullptr, qkv,
                                                           BN, QKV3, DIMC, 0);
    // 2) fused scores + register softmax + bias + AV
    attn_fused_kernel<<<NBLK, 224, FA_SMEM_BYTES>>>(qkv, sa, ao);
    // 3) output projection + bias (split-bf16)
    gemm_bf16s_kernel<<<dim3(DIMC / TBN, BN / TBM), 256>>>(ao, Wproj, bproj, out,
                                                           BN, DIMC, DIMC, 1);
}

// round 17
// speedup vs baseline: 1.2285x; 1.2285x over previous
#include <cuda_runtime.h>
#include <cuda_bf16.h>
#include <math.h>

#define BATCH 64
#define SEQ   196
#define DIMC  768
#define HEADS 12
#define HD    64
#define QKV3  2304           // 3*DIMC
#define BN    (BATCH*SEQ)    // 12544
#define SCALE 0.125f         // HD^-0.5
#define NBLK  (BATCH*HEADS*2)  // 1536 (b,h,q-half)

// ---------------- scratch (no allocation allowed; __device__ globals) -------
__device__ float g_qkv[(size_t)BATCH * SEQ * QKV3];          // [BN, 2304]
__device__ float g_ao[(size_t)BATCH * SEQ * DIMC];           // [BN, 768]

// ---------------- helpers -----------------------------------------------------
__device__ __forceinline__ unsigned f2tf32(float x) {
    unsigned u;
    asm volatile("cvt.rna.tf32.f32 %0, %1;" : "=r"(u) : "f"(x));
    return u;
}

__device__ __forceinline__ void mma_tf32(float (&d)[4], const unsigned (&a)[4],
                                         const unsigned (&b)[2]) {
    asm volatile(
        "mma.sync.aligned.m16n8k8.row.col.f32.tf32.tf32.f32 "
        "{%0,%1,%2,%3}, {%4,%5,%6,%7}, {%8,%9}, {%0,%1,%2,%3};\n"
        : "+f"(d[0]), "+f"(d[1]), "+f"(d[2]), "+f"(d[3])
        : "r"(a[0]), "r"(a[1]), "r"(a[2]), "r"(a[3]), "r"(b[0]), "r"(b[1]));
}

__device__ __forceinline__ void ldsm_x4(unsigned& r0, unsigned& r1,
                                        unsigned& r2, unsigned& r3,
                                        unsigned addr) {
    asm volatile(
        "ldmatrix.sync.aligned.m8n8.x4.shared.b16 {%0,%1,%2,%3}, [%4];\n"
        : "=r"(r0), "=r"(r1), "=r"(r2), "=r"(r3) : "r"(addr));
}

// ---------------- TF32 GEMM with ldmatrix fragments --------------------------
// 128x128 block tile, BK=32, 256 threads = 8 warps (4M x 2N), warp 32x64.
// A smem [m][k] stride 36; B smem TRANSPOSED [n][k] stride 36.
// Fragments via ldmatrix.x4: A 8/tile/warp, B 16/tile/warp (was 96 LDS.32).
#define TBM 128
#define TBN 128
#define TBK 32
#define TR_STRIDE 36    // words; rows at 4-word bank offsets -> LDSM conflict-free

__global__ __launch_bounds__(256, 2)
void gemm_tf32_kernel(const float* __restrict__ A, const float* __restrict__ B,
                      const float* __restrict__ bias, float* __restrict__ C,
                      int M, int N, int K, int useBias)
{
    __shared__ unsigned As[TBM * TR_STRIDE];    // [m][k]
    __shared__ unsigned Bt[TBN * TR_STRIDE];    // [n][k]

    const int tid  = threadIdx.x;
    const int lane = tid & 31;
    const int warp = tid >> 5;
    const int r    = lane >> 2;
    const int tq   = lane & 3;
    const int warpM = (warp & 3) * 32;     // 4 warps in M
    const int warpN = (warp >> 2) * 64;    // 2 warps in N

    const int n0 = blockIdx.x * TBN;
    const int m0 = blockIdx.y * TBM;

    const unsigned asBase = (unsigned)__cvta_generic_to_shared(As);
    const unsigned btBase = (unsigned)__cvta_generic_to_shared(Bt);

    // ldmatrix lane-address components (word offsets within tile)
    // A tiles: rows rb + (l&15), k-chunk (l>>4)*4
    const int aRow  = warpM + (lane & 15);
    const int aKoff = (lane >> 4) * 4;
    // B tiles: rows cb + (l&7) + ((l&16)>>1), k-chunk ((l&8)>>1)
    const int bRow  = warpN + (lane & 7) + ((lane & 16) >> 1);
    const int bKoff = (lane & 8) >> 1;

    float acc[2][8][4];
#pragma unroll
    for (int i = 0; i < 2; i++)
#pragma unroll
        for (int j = 0; j < 8; j++)
#pragma unroll
            for (int t = 0; t < 4; t++) acc[i][j][t] = 0.f;

    for (int k0 = 0; k0 < K; k0 += TBK) {
        // ---- A tile: 128 rows x 32 k, cvt at store (4 float4 per thread)
#pragma unroll
        for (int i = 0; i < 4; i++) {
            int f   = tid + i * 256;
            int row = f >> 3;
            int kk  = (f & 7) * 4;
            float4 v = *(const float4*)(A + (size_t)(m0 + row) * K + k0 + kk);
            uint4 o;
            o.x = f2tf32(v.x); o.y = f2tf32(v.y);
            o.z = f2tf32(v.z); o.w = f2tf32(v.w);
            *(uint4*)&As[row * TR_STRIDE + kk] = o;
        }
        // ---- B tile TRANSPOSED: Bt[n][k] = tf32(B[k0+k][n0+n]).
        //      4 positions/thread; each: 4 coalesced LDG.32 down a column.
#pragma unroll
        for (int i = 0; i < 4; i++) {
            int p  = tid + i * 256;           // 0..1023
            int n  = p & 127;
            int kq = p >> 7;                  // 0..7
            const float* bp = B + (size_t)(k0 + kq * 4) * N + n0 + n;
            uint4 o;
            o.x = f2tf32(bp[0]);
            o.y = f2tf32(bp[(size_t)N]);
            o.z = f2tf32(bp[(size_t)2 * N]);
            o.w = f2tf32(bp[(size_t)3 * N]);
            *(uint4*)&Bt[n * TR_STRIDE + kq * 4] = o;
        }
        __syncthreads();

        // ---- compute: 4 k-steps of 8, fragments via ldmatrix.x4
#pragma unroll
        for (int ks = 0; ks < 4; ks++) {
            int kb = ks * 8;
            unsigned bfrag[8][2];
#pragma unroll
            for (int pr = 0; pr < 4; pr++) {   // nt pair: covers nt=2pr, 2pr+1
                unsigned addr = btBase +
                    (unsigned)(((bRow + pr * 16) * TR_STRIDE + kb + bKoff) * 4);
                ldsm_x4(bfrag[2 * pr][0], bfrag[2 * pr][1],
                        bfrag[2 * pr + 1][0], bfrag[2 * pr + 1][1], addr);
            }
#pragma unroll
            for (int mt = 0; mt < 2; mt++) {
                unsigned af[4];
                unsigned addr = asBase +
                    (unsigned)(((aRow + mt * 16) * TR_STRIDE + kb + aKoff) * 4);
                ldsm_x4(af[0], af[1], af[2], af[3], addr);
#pragma unroll
                for (int nt = 0; nt < 8; nt++)
                    mma_tf32(acc[mt][nt], af, bfrag[nt]);
            }
        }
        __syncthreads();
    }

    // ---- epilogue: c0/c1 at (r, 2tq), c2/c3 at (r+8, 2tq)
#pragma unroll
    for (int mt = 0; mt < 2; mt++) {
#pragma unroll
        for (int nt = 0; nt < 8; nt++) {
            int row = m0 + warpM + mt * 16 + r;
            int col = n0 + warpN + nt * 8 + 2 * tq;
            float2 lo = make_float2(acc[mt][nt][0], acc[mt][nt][1]);
            float2 hi = make_float2(acc[mt][nt][2], acc[mt][nt][3]);
            if (useBias) {
                float2 bv = *(const float2*)(bias + col);
                lo.x += bv.x; lo.y += bv.y;
                hi.x += bv.x; hi.y += bv.y;
            }
            *(float2*)(C + (size_t)row * N + col)       = lo;
            *(float2*)(C + (size_t)(row + 8) * N + col) = hi;
        }
    }
}

// ---------------- fused attention: scores + reg softmax + bias + AV ---------
// (R14 kernel, unchanged — verified numerics)
#define FA_KV_OFF 7616                            // words (112*68)
#define FA_SMEM_WORDS (FA_KV_OFF + 208 * 72)      // 22592
#define FA_SMEM_BYTES (FA_SMEM_WORDS * 4)         // 90368

__global__ __launch_bounds__(224, 2)
void attn_fused_kernel(const float* __restrict__ qkv,
                       const float* __restrict__ sa,
                       float* __restrict__ ao)
{
    extern __shared__ unsigned smu[];
    unsigned* Qs = smu;                 // [112][68], SCALE pre-folded
    unsigned* Ks = smu + FA_KV_OFF;     // [208][68] (scores phase)
    unsigned* Vs = smu + FA_KV_OFF;     // [208][72] tf32 (AV phase)

    const int bid = blockIdx.x;
    const int bh = bid >> 1, qb = bid & 1;
    const int b = bh / HEADS, h = bh % HEADS;
    const int q0 = qb * 98;

    const float* Qg = qkv + (size_t)b * SEQ * QKV3 + h * HD;
    const float* Kg = Qg + DIMC;
    const float* Vg = Qg + 2 * DIMC;

    const int tid  = threadIdx.x;
    const int lane = tid & 31;
    const int warp = tid >> 5;
    const int r    = lane >> 2;
    const int tq   = lane & 3;

    for (int i = tid; i < 112 * 16; i += 224) {
        int row = i >> 4, c4 = (i & 15) * 4;
        float4 v = make_float4(0.f, 0.f, 0.f, 0.f);
        if (row < 98) v = *(const float4*)(Qg + (size_t)(q0 + row) * QKV3 + c4);
        uint4 o;
        o.x = f2tf32(v.x * SCALE); o.y = f2tf32(v.y * SCALE);
        o.z = f2tf32(v.z * SCALE); o.w = f2tf32(v.w * SCALE);
        *(uint4*)&Qs[row * 68 + c4] = o;
    }
    for (int i = tid; i < 208 * 16; i += 224) {
        int row = i >> 4, c4 = (i & 15) * 4;
        float4 v = make_float4(0.f, 0.f, 0.f, 0.f);
        if (row < SEQ) v = *(const float4*)(Kg + (size_t)row * QKV3 + c4);
        uint4 o;
        o.x = f2tf32(v.x); o.y = f2tf32(v.y);
        o.z = f2tf32(v.z); o.w = f2tf32(v.w);
        *(uint4*)&Ks[row * 68 + c4] = o;
    }
    __syncthreads();

    float acc[13][2][4];
#pragma unroll
    for (int mg = 0; mg < 13; mg++)
#pragma unroll
        for (int mt = 0; mt < 2; mt++)
#pragma unroll
            for (int t = 0; t < 4; t++) acc[mg][mt][t] = 0.f;

    const int rb = warp * 16;
#pragma unroll
    for (int ks = 0; ks < 8; ks++) {
        int kb = ks * 8;
        unsigned af[4];
        af[0] = Qs[(rb + r)     * 68 + kb + tq];
        af[1] = Qs[(rb + r + 8) * 68 + kb + tq];
        af[2] = Qs[(rb + r)     * 68 + kb + tq + 4];
        af[3] = Qs[(rb + r + 8) * 68 + kb + tq + 4];
#pragma unroll
        for (int mg = 0; mg < 13; mg++)
#pragma unroll
            for (int mt = 0; mt < 2; mt++) {
                int cb = mg * 16 + mt * 8;
                unsigned bf[2];
                bf[0] = Ks[(cb + r) * 68 + kb + tq];
                bf[1] = Ks[(cb + r) * 68 + kb + tq + 4];
                mma_tf32(acc[mg][mt], af, bf);
            }
    }

    float mx0 = -INFINITY, mx1 = -INFINITY;
#pragma unroll
    for (int mg = 0; mg < 13; mg++)
#pragma unroll
        for (int mt = 0; mt < 2; mt++)
#pragma unroll
            for (int j = 0; j < 2; j++) {
                bool valid = (mg < 12) || (mt == 0 && (2 * tq + j) < 4);
                if (valid) {
                    mx0 = fmaxf(mx0, acc[mg][mt][j]);
                    mx1 = fmaxf(mx1, acc[mg][mt][2 + j]);
                }
            }
    mx0 = fmaxf(mx0, __shfl_xor_sync(0xffffffffu, mx0, 1));
    mx0 = fmaxf(mx0, __shfl_xor_sync(0xffffffffu, mx0, 2));
    mx1 = fmaxf(mx1, __shfl_xor_sync(0xffffffffu, mx1, 1));
    mx1 = fmaxf(mx1, __shfl_xor_sync(0xffffffffu, mx1, 2));

    float sum0 = 0.f, sum1 = 0.f;
#pragma unroll
    for (int mg = 0; mg < 13; mg++)
#pragma unroll
        for (int mt = 0; mt < 2; mt++)
#pragma unroll
            for (int j = 0; j < 2; j++) {
                bool valid = (mg < 12) || (mt == 0 && (2 * tq + j) < 4);
                float e0 = valid ? __expf(acc[mg][mt][j]     - mx0) : 0.f;
                float e1 = valid ? __expf(acc[mg][mt][2 + j] - mx1) : 0.f;
                acc[mg][mt][j]     = e0;
                acc[mg][mt][2 + j] = e1;
                sum0 += e0;
                sum1 += e1;
            }
    sum0 += __shfl_xor_sync(0xffffffffu, sum0, 1);
    sum0 += __shfl_xor_sync(0xffffffffu, sum0, 2);
    sum1 += __shfl_xor_sync(0xffffffffu, sum1, 1);
    sum1 += __shfl_xor_sync(0xffffffffu, sum1, 2);
    const float inv0 = 1.f / sum0;
    const float inv1 = 1.f / sum1;

    const int row0 = rb + r, row1 = rb + r + 8;
    const float* ar0 = sa + ((size_t)h * SEQ + q0 + row0) * SEQ;
    const float* ar1 = sa + ((size_t)h * SEQ + q0 + row1) * SEQ;
    const bool rOk0 = row0 < 98, rOk1 = row1 < 98;
#pragma unroll
    for (int mg = 0; mg < 13; mg++)
#pragma unroll
        for (int mt = 0; mt < 2; mt++) {
            int c = mg * 16 + mt * 8 + 2 * tq;
#pragma unroll
            for (int j = 0; j < 2; j++) {
                bool valid = (mg < 12) || (mt == 0 && (2 * tq + j) < 4);
                float a0 = (valid && rOk0) ? ar0[c + j] : 0.f;
                float a1 = (valid && rOk1) ? ar1[c + j] : 0.f;
                acc[mg][mt][j]     = valid ? acc[mg][mt][j]     * inv0 + a0 : 0.f;
                acc[mg][mt][2 + j] = valid ? acc[mg][mt][2 + j] * inv1 + a1 : 0.f;
            }
        }

    __syncthreads();   // all warps done reading Ks
    for (int i = tid; i < 208 * 16; i += 224) {
        int row = i >> 4, c4 = (i & 15) * 4;
        float4 v = make_float4(0.f, 0.f, 0.f, 0.f);
        if (row < SEQ) v = *(const float4*)(Vg + (size_t)row * QKV3 + c4);
        uint4 o;
        o.x = f2tf32(v.x); o.y = f2tf32(v.y);
        o.z = f2tf32(v.z); o.w = f2tf32(v.w);
        *(uint4*)&Vs[row * 72 + c4] = o;
    }
    __syncthreads();

    float out[8][4];
#pragma unroll
    for (int nt = 0; nt < 8; nt++)
#pragma unroll
        for (int t = 0; t < 4; t++) out[nt][t] = 0.f;

    const int srcA = (lane & ~3) | (tq >> 1);
    const int srcB = srcA + 2;
    const bool jsel = (tq & 1);

#pragma unroll
    for (int mg = 0; mg < 13; mg++) {
#pragma unroll
        for (int mt = 0; mt < 2; mt++) {
            float p0a = __shfl_sync(0xffffffffu, acc[mg][mt][0], srcA);
            float p1a = __shfl_sync(0xffffffffu, acc[mg][mt][1], srcA);
            float p0b = __shfl_sync(0xffffffffu, acc[mg][mt][0], srcB);
            float p1b = __shfl_sync(0xffffffffu, acc[mg][mt][1], srcB);
            float p2a = __shfl_sync(0xffffffffu, acc[mg][mt][2], srcA);
            float p3a = __shfl_sync(0xffffffffu, acc[mg][mt][3], srcA);
            float p2b = __shfl_sync(0xffffffffu, acc[mg][mt][2], srcB);
            float p3b = __shfl_sync(0xffffffffu, acc[mg][mt][3], srcB);
            unsigned af[4];
            af[0] = f2tf32(jsel ? p1a : p0a);
            af[1] = f2tf32(jsel ? p3a : p2a);
            af[2] = f2tf32(jsel ? p1b : p0b);
            af[3] = f2tf32(jsel ? p3b : p2b);
            const int kb = mg * 16 + mt * 8;
#pragma unroll
            for (int nt = 0; nt < 8; nt++) {
                unsigned bf[2];
                bf[0] = Vs[(kb + tq)     * 72 + nt * 8 + r];
                bf[1] = Vs[(kb + tq + 4) * 72 + nt * 8 + r];
                mma_tf32(out[nt], af, bf);
            }
        }
    }

    float* og = ao + (size_t)b * SEQ * DIMC + h * HD;
#pragma unroll
    for (int nt = 0; nt < 8; nt++) {
        int c = nt * 8 + 2 * tq;
        if (rOk0)
            *(float2*)(og + (size_t)(q0 + row0) * DIMC + c) =
                make_float2(out[nt][0], out[nt][1]);
        if (rOk1)
            *(float2*)(og + (size_t)(q0 + row1) * DIMC + c) =
                make_float2(out[nt][2], out[nt][3]);
    }
}

// ---------------- launch ----------------------------------------------------
extern "C" void kernel_launch(void* const* d_in, const int* in_sizes, int n_in,
                              void* d_out, int out_size)
{
    const float* x     = (const float*)d_in[0];  // [64,196,768]
    const float* Wqkv  = (const float*)d_in[1];  // [768,2304]
    const float* sa    = (const float*)d_in[2];  // [1,12,196,196]
    const float* Wproj = (const float*)d_in[3];  // [768,768]
    const float* bproj = (const float*)d_in[4];  // [768]
    float* out = (float*)d_out;                  // [64,196,768]

    void *p_qkv, *p_ao;
    cudaGetSymbolAddress(&p_qkv, g_qkv);
    cudaGetSymbolAddress(&p_ao, g_ao);
    float* qkv = (float*)p_qkv;
    float* ao  = (float*)p_ao;

    static int smem_set = 0;
    if (!smem_set) {
        cudaFuncSetAttribute(attn_fused_kernel,
                             cudaFuncAttributeMaxDynamicSharedMemorySize,
                             FA_SMEM_BYTES);
        smem_set = 1;
    }

    // 1) QKV GEMM (tf32 + ldmatrix fragments)
    gemm_tf32_kernel<<<dim3(QKV3 / TBN, BN / TBM), 256>>>(x, Wqkv, nullptr, qkv,
                                                          BN, QKV3, DIMC, 0);
    // 2) fused scores + register softmax + bias + AV
    attn_fused_kernel<<<NBLK, 224, FA_SMEM_BYTES>>>(qkv, sa, ao);
    // 3) output projection + bias (tf32 + ldmatrix fragments)
    gemm_tf32_kernel<<<dim3(DIMC / TBN, BN / TBM), 256>>>(ao, Wproj, bproj, out,
                                                          BN, DIMC, DIMC, 1);
}